// round 12
// baseline (speedup 1.0000x reference)
#include <cuda_runtime.h>

#define HID 50
#define GP  224      // 4 types * 56 j-slots
#define NGG 32       // gate-groups of 7
#define K4N 13       // k padded 50->52, 4 per float4
#define BT  16
#define GS  17       // gates row stride
#define NTHREADS 512 // 16 warps = 2 groups of 8

typedef unsigned long long u64;

__device__ __forceinline__ void ffma2(u64& d, u64 a, u64 b) {
    asm("fma.rn.f32x2 %0, %1, %2, %3;" : "=l"(d) : "l"(a), "l"(b), "l"(d));
}
__device__ __forceinline__ float f2lo(u64 a) { return __uint_as_float((unsigned)a); }
__device__ __forceinline__ float f2hi(u64 a) { return __uint_as_float((unsigned)(a >> 32)); }

__device__ __forceinline__ float tanh_a(float x) {
    float r;
    asm("tanh.approx.f32 %0, %1;" : "=f"(r) : "f"(x));
    return r;
}
__device__ __forceinline__ float sigmoid_a(float x) {
    return fmaf(0.5f, tanh_a(0.5f * x), 0.5f);
}

__global__ void __launch_bounds__(NTHREADS, 1)
seq2seq_kernel(const float* __restrict__ source,
               const float* __restrict__ eWih, const float* __restrict__ eWhh,
               const float* __restrict__ eBih, const float* __restrict__ eBhh,
               const float* __restrict__ dWih, const float* __restrict__ dWhh,
               const float* __restrict__ dBih, const float* __restrict__ dBhh,
               const float* __restrict__ fcW,  const float* __restrict__ fcB,
               float* __restrict__ out, int S, int T)
{
    extern __shared__ char smem_raw[];
    float4* wenc  = (float4*)smem_raw;                // [(k4*7+i)*32 + gg]
    float4* wdec  = wenc + K4N * 7 * NGG;
    float4* h4    = wdec + K4N * 7 * NGG;             // [(k4*2+par)*8 + pos]
    float*  gatesf= (float*)(h4 + K4N * 2 * 8);       // [g(224)][GS]
    float*  xdec  = gatesf + GP * GS;                 // [BT]
    float*  fcw   = xdec + BT;                        // [HID]
    float*  fcb   = fcw + HID;                        // [2]
    float*  srcsT = fcb + 2;                          // [S][BT]
    float*  h4f   = (float*)h4;

    const int tid  = threadIdx.x;
    const int lane = tid & 31;
    const int wrp  = tid >> 5;                        // [0,16)
    const int b0g  = blockIdx.x * BT;

    // ---- two independent groups: grp 0 owns rows 0-7, grp 1 rows 8-15
    const int grp  = wrp >> 3;                        // {0,1}
    const int w8   = wrp & 7;                         // warp within group
    const int barid = grp + 1;                        // named barrier id

    // GEMM tile: thread = (1 row of its group, 7 gates); warp owns gg {4w8..4w8+3}
    const int ggl  = lane & 3;
    const int rloc = lane >> 2;                       // [0,8)
    const int gg   = w8 * 4 + ggl;                    // [0,32)
    const int gbase= gg * 7;
    const int b    = grp * 8 + rloc;                  // global row
    const int hpar = b & 1;
    const int hpos = b >> 1;

    // ---- stage weights, interleaved by gate-group
    auto stage_w = [&](float4* dst, const float* Whh) {
        for (int idx = tid; idx < K4N * GP; idx += NTHREADS) {
            int k4 = idx / GP, g = idx % GP;
            int ggi = g / 7, ii = g % 7;
            int ty = g / 56, j = g % 56;
            float4 v = make_float4(0.f, 0.f, 0.f, 0.f);
            if (j < HID) {
                int row = ty * HID + j;
                #pragma unroll
                for (int c = 0; c < 4; c++) {
                    int k = 4 * k4 + c;
                    if (k < HID) ((float*)&v)[c] = Whh[row * HID + k];
                }
            }
            dst[(k4 * 7 + ii) * NGG + ggi] = v;
        }
    };
    stage_w(wenc, eWhh);
    stage_w(wdec, dWhh);
    for (int i = tid; i < K4N * 2 * 8; i += NTHREADS) h4[i] = make_float4(0.f, 0.f, 0.f, 0.f);
    if (tid < BT)  xdec[tid] = 0.f;
    if (tid < HID) fcw[tid] = fcW[tid];
    if (tid == 0)  fcb[0] = fcB[0];
    for (int idx = tid; idx < BT * S; idx += NTHREADS) {
        int bl = idx / S, t = idx % S;
        srcsT[t * BT + bl] = source[(size_t)(b0g + bl) * S + t];
    }

    // ---- per-thread constants
    float biasr[7], wihr[7];
    auto stage_c = [&](const float* Wih, const float* Bih, const float* Bhh) {
        #pragma unroll
        for (int i = 0; i < 7; i++) {
            int g = gbase + i, ty = g / 56, j = g % 56;
            if (j < HID) { int r = ty * HID + j; biasr[i] = Bih[r] + Bhh[r]; wihr[i] = Wih[r]; }
            else         { biasr[i] = 0.f; wihr[i] = 0.f; }
        }
    };
    stage_c(eWih, eBih, eBhh);

    // update mapping (group-local): tloc in [0,256)
    const int tloc = tid & 255;
    const int bu0 = grp * 8 + (tloc & 7), ju0 = tloc >> 3;        // j 0..31
    const int bu1 = bu0,                  ju1 = 32 + (tloc >> 3); // j 32..49
    const bool has1 = tloc < 8 * (HID - 32);                      // tloc < 144
    float c0 = 0.f, c1 = 0.f;
    __syncthreads();   // ONLY full-CTA barrier; groups are independent after this

    const ulonglong2* h2 = (const ulonglong2*)h4;

    #define GBAR() asm volatile("bar.sync %0, 256;" :: "r"(barid) : "memory")

    auto gemm = [&](const float4* wp, float xv) {
        u64 acc[7];
        #pragma unroll
        for (int i = 0; i < 7; i++)
            acc[i] = (u64)__float_as_uint(fmaf(xv, wihr[i], biasr[i]));
        const ulonglong2* w2 = (const ulonglong2*)wp;
        #pragma unroll
        for (int k4 = 0; k4 < K4N; k4++) {
            ulonglong2 hv = h2[(k4 * 2 + hpar) * 8 + hpos];   // 8 distinct f4: 2 wf
            #pragma unroll
            for (int i = 0; i < 7; i++) {
                ulonglong2 wv = w2[(k4 * 7 + i) * NGG + gg];  // 4 consecutive f4: 1 wf
                ffma2(acc[i], wv.x, hv.x);
                ffma2(acc[i], wv.y, hv.y);
            }
        }
        #pragma unroll
        for (int i = 0; i < 7; i++) {
            u64 a = acc[i];
            gatesf[(gbase + i) * GS + b] = f2lo(a) + f2hi(a);
        }
    };

    auto upd_one = [&](int bb, int j, float& c) {
        float gi  = gatesf[(0 * 56 + j) * GS + bb];
        float gf  = gatesf[(1 * 56 + j) * GS + bb];
        float gg_ = gatesf[(2 * 56 + j) * GS + bb];
        float go  = gatesf[(3 * 56 + j) * GS + bb];
        float iv = sigmoid_a(gi);
        float fv = sigmoid_a(gf);
        float gv = tanh_a(gg_);
        float ov = sigmoid_a(go);
        c = fmaf(fv, c, iv * gv);
        float h = ov * tanh_a(c);
        h4f[((j >> 2) * 2 + (bb & 1)) * 32 + (bb >> 1) * 4 + (j & 3)] = h;
    };

    // ================= encoder =================
    for (int t = 0; t < S; t++) {
        gemm(wenc, srcsT[t * BT + b]);
        GBAR();
        upd_one(bu0, ju0, c0);
        if (has1) upd_one(bu1, ju1, c1);
        GBAR();
    }

    // ================= decoder =================
    stage_c(dWih, dBih, dBhh);
    for (int t = 0; t < T; t++) {
        gemm(wdec, xdec[b]);
        GBAR();
        upd_one(bu0, ju0, c0);
        if (has1) upd_one(bu1, ju1, c1);
        GBAR();

        if (w8 == 0) {   // group's fc warp: 8 rows, 4 lanes each
            const int bfc = grp * 8 + (lane & 7);
            const int hhf = lane >> 3;                 // [0,4)
            float s = 0.f;
            #pragma unroll
            for (int jj = 0; jj < 13; jj++) {
                int jq = hhf * 13 + jj;
                if (jq < HID)
                    s = fmaf(h4f[((jq >> 2) * 2 + (bfc & 1)) * 32 + (bfc >> 1) * 4 + (jq & 3)],
                             fcw[jq], s);
            }
            s += __shfl_xor_sync(0xffffffffu, s, 8);
            s += __shfl_xor_sync(0xffffffffu, s, 16);
            if (hhf == 0) {
                float y = s + fcb[0];
                xdec[bfc] = y;
                out[(size_t)(b0g + bfc) * T + t] = y;
            }
        }
        GBAR();
    }
    #undef GBAR
}

extern "C" void kernel_launch(void* const* d_in, const int* in_sizes, int n_in,
                              void* d_out, int out_size)
{
    const float* source = (const float*)d_in[0];
    const float* eWih = (const float*)d_in[1];
    const float* eWhh = (const float*)d_in[2];
    const float* eBih = (const float*)d_in[3];
    const float* eBhh = (const float*)d_in[4];
    const float* dWih = (const float*)d_in[5];
    const float* dWhh = (const float*)d_in[6];
    const float* dBih = (const float*)d_in[7];
    const float* dBhh = (const float*)d_in[8];
    const float* fcW  = (const float*)d_in[9];
    const float* fcB  = (const float*)d_in[10];
    float* out = (float*)d_out;

    const int B = 2048;
    const int S = in_sizes[0] / B;   // 512
    const int T = out_size   / B;    // 256

    size_t sm = sizeof(float4) * (size_t)(K4N * 7 * NGG * 2 + K4N * 2 * 8)
              + sizeof(float)  * (size_t)(GP * GS + BT + HID + 2)
              + sizeof(float)  * (size_t)BT * S;

    cudaFuncSetAttribute(seq2seq_kernel, cudaFuncAttributeMaxDynamicSharedMemorySize, (int)sm);
    seq2seq_kernel<<<B / BT, NTHREADS, sm>>>(source, eWih, eWhh, eBih, eBhh,
                                             dWih, dWhh, dBih, dBhh, fcW, fcB,
                                             out, S, T);
}

// round 13
// speedup vs baseline: 1.4450x; 1.4450x over previous
#include <cuda_runtime.h>

#define HID 50
#define JP  64          // padded gate j (4 types x 64)
#define K4N 13          // k in groups of 4 (k 0..51; k=50 is the x slot)
#define KPN 26          // k-pairs
#define BT  16
#define GSF 18          // gates float stride per gate row
#define NTHREADS 512    // 16 warps
#define HB  (KPN * 16)  // u64 per h buffer

typedef unsigned long long u64;

__device__ __forceinline__ void ffma2(u64& d, u64 a, u64 b) {
    asm("fma.rn.f32x2 %0, %1, %2, %3;" : "=l"(d) : "l"(a), "l"(b), "l"(d));
}
__device__ __forceinline__ float f2lo(u64 a) { return __uint_as_float((unsigned)a); }
__device__ __forceinline__ float f2hi(u64 a) { return __uint_as_float((unsigned)(a >> 32)); }

__device__ __forceinline__ float tanh_a(float x) {
    float r;
    asm("tanh.approx.f32 %0, %1;" : "=f"(r) : "f"(x));
    return r;
}
__device__ __forceinline__ float sigmoid_a(float x) {
    return fmaf(0.5f, tanh_a(0.5f * x), 0.5f);
}

__global__ void __launch_bounds__(NTHREADS, 1)
seq2seq_kernel(const float* __restrict__ source,
               const float* __restrict__ eWih, const float* __restrict__ eWhh,
               const float* __restrict__ eBih, const float* __restrict__ eBhh,
               const float* __restrict__ dWih, const float* __restrict__ dWhh,
               const float* __restrict__ dBih, const float* __restrict__ dBhh,
               const float* __restrict__ fcW,  const float* __restrict__ fcB,
               float* __restrict__ out, int S, int T)
{
    extern __shared__ char smem_raw[];
    float4* wenc  = (float4*)smem_raw;                // [(k4*4+jj)*64 + ggq]
    float4* wdec  = wenc + K4N * 4 * JP;
    u64*    hbuf  = (u64*)(wdec + K4N * 4 * JP);      // [2][kp*16 + row]
    float*  gatesf= (float*)(hbuf + 2 * HB);          // [g(256)][GSF]
    float*  fcw   = gatesf + 4 * JP * GSF;            // [HID]
    float*  fcb   = fcw + HID;                        // [2]
    float*  srcsT = fcb + 2;                          // [S][BT]

    const int tid  = threadIdx.x;
    const int lane = tid & 31;
    const int wrp  = tid >> 5;                        // [0,16)
    const int b0g  = blockIdx.x * BT;

    // thread tile: (ty, 4 gates jbase..jbase+3) x (2 rows)
    const int ty    = wrp >> 2;
    const int j4h   = (wrp >> 1) & 1;
    const int rq2h  = wrp & 1;
    const int j4l   = lane & 7;
    const int rq2l  = lane >> 3;                      // [0,4)
    const int j4    = j4h * 8 + j4l;                  // [0,16)
    const int rq2   = rq2h * 4 + rq2l;                // [0,8): row pair
    const int ggq   = ty * 16 + j4;                   // [0,64)
    const int jbase = j4 * 4;
    const int gbase = ty * JP + jbase;
    const int row0  = rq2 * 2, row1 = row0 + 1;

    // ---- stage weights: w4[idx], idx = (k4*4+jj)*JP + ggq
    //      float4 = 4 consecutive k for gate (ty, j4*4+jj); k==50 -> Wih column
    auto stage_w = [&](float4* dst, const float* Whh, const float* Wih) {
        for (int idx = tid; idx < K4N * 4 * JP; idx += NTHREADS) {
            int k4 = idx / (4 * JP);
            int r  = idx % (4 * JP);
            int jj = r / JP, gq = r % JP;
            int tyq = gq >> 4, j = (gq & 15) * 4 + jj;
            float4 v = make_float4(0.f, 0.f, 0.f, 0.f);
            if (j < HID) {
                int rw = tyq * HID + j;
                #pragma unroll
                for (int c = 0; c < 4; c++) {
                    int k = k4 * 4 + c;
                    if (k < HID)       ((float*)&v)[c] = Whh[rw * HID + k];
                    else if (k == HID) ((float*)&v)[c] = Wih[rw];   // x slot
                }
            }
            dst[idx] = v;
        }
    };
    stage_w(wenc, eWhh, eWih);
    stage_w(wdec, dWhh, dWih);
    for (int i = tid; i < 2 * HB; i += NTHREADS) hbuf[i] = 0ull;
    if (tid < HID) fcw[tid] = fcW[tid];
    if (tid == 0)  fcb[0] = fcB[0];
    for (int idx = tid; idx < BT * S; idx += NTHREADS) {
        int bl = idx / S, t = idx % S;
        srcsT[t * BT + bl] = source[(size_t)(b0g + bl) * S + t];
    }

    // per-thread bias
    float biasr[4];
    auto stage_b = [&](const float* Bih, const float* Bhh) {
        #pragma unroll
        for (int jj = 0; jj < 4; jj++) {
            int j = jbase + jj;
            if (j < HID) { int r = ty * HID + j; biasr[jj] = Bih[r] + Bhh[r]; }
            else biasr[jj] = 0.f;
        }
    };
    stage_b(eBih, eBhh);

    // update mapping (r10): cell0 j<32 all threads; cell1 j in [32,50) for tid<288
    const int bu0 = tid & 15,  ju0 = tid >> 4;
    const int ju1 = ju0 + 32;
    const bool has1 = (tid + 512) < BT * HID;
    float c0 = 0.f, c1 = 0.f;
    __syncthreads();
    // x[0] into h slot k=50 (kp=25, lo half) of buffer 0
    if (tid < BT) ((float*)hbuf)[25 * 32 + tid * 2] = srcsT[0 * BT + tid];
    __syncthreads();

    auto gemm = [&](const float4* wp, const u64* hb) {
        u64 acc[4][2];
        #pragma unroll
        for (int jj = 0; jj < 4; jj++) { acc[jj][0] = 0ull; acc[jj][1] = 0ull; }
        const ulonglong2* w2 = (const ulonglong2*)wp;
        const ulonglong2* h2 = (const ulonglong2*)hb;
        #pragma unroll
        for (int k4 = 0; k4 < K4N; k4++) {
            // h2 idx in u64: (kp*16 + row); LDS.128 grabs both rows of a kp
            ulonglong2 hva = h2[(k4 * 2 + 0) * 8 + rq2];  // kp=2k4  : .x=row0 .y=row1
            ulonglong2 hvb = h2[(k4 * 2 + 1) * 8 + rq2];  // kp=2k4+1
            #pragma unroll
            for (int jj = 0; jj < 4; jj++) {
                ulonglong2 wv = w2[(k4 * 4 + jj) * (JP / 2) * 2 + ggq]; // dense 128B line
                ffma2(acc[jj][0], wv.x, hva.x);
                ffma2(acc[jj][0], wv.y, hvb.x);
                ffma2(acc[jj][1], wv.x, hva.y);
                ffma2(acc[jj][1], wv.y, hvb.y);
            }
        }
        #pragma unroll
        for (int jj = 0; jj < 4; jj++) {
            int g = gbase + jj;
            gatesf[g * GSF + row0] = f2lo(acc[jj][0]) + f2hi(acc[jj][0]) + biasr[jj];
            gatesf[g * GSF + row1] = f2lo(acc[jj][1]) + f2hi(acc[jj][1]) + biasr[jj];
        }
    };

    auto upd_one = [&](int b, int j, float& c, float* hnf) {
        float gi  = gatesf[(0 * JP + j) * GSF + b];
        float gf  = gatesf[(1 * JP + j) * GSF + b];
        float gg_ = gatesf[(2 * JP + j) * GSF + b];
        float go  = gatesf[(3 * JP + j) * GSF + b];
        float iv = sigmoid_a(gi);
        float fv = sigmoid_a(gf);
        float gv = tanh_a(gg_);
        float ov = sigmoid_a(go);
        c = fmaf(fv, c, iv * gv);
        float h = ov * tanh_a(c);
        hnf[(j >> 1) * 32 + b * 2 + (j & 1)] = h;   // h2u[kp*16+row] float view
    };

    int pb = 0;

    // ================= encoder =================
    for (int t = 0; t < S; t++) {
        gemm(wenc, hbuf + pb * HB);
        __syncthreads();
        float* hnf = (float*)(hbuf + (pb ^ 1) * HB);
        upd_one(bu0, ju0, c0, hnf);
        if (has1) upd_one(bu0, ju1, c1, hnf);
        if (tid < BT) {                               // x_{t+1} into slot k=50
            float xv = (t + 1 < S) ? srcsT[(t + 1) * BT + tid] : 0.f;
            hnf[25 * 32 + tid * 2] = xv;              // decoder x0 = 0 covered
        }
        pb ^= 1;
        __syncthreads();
    }

    // ================= decoder =================
    stage_b(dBih, dBhh);
    for (int t = 0; t < T; t++) {
        gemm(wdec, hbuf + pb * HB);
        __syncthreads();
        float* hnf = (float*)(hbuf + (pb ^ 1) * HB);
        upd_one(bu0, ju0, c0, hnf);
        if (has1) upd_one(bu0, ju1, c1, hnf);
        __syncthreads();                              // h_t visible

        if (wrp == 0) {                               // fc + feed y back as next x
            const int bfc = lane & 15;
            const int hhf = lane >> 4;
            float s = 0.f;
            #pragma unroll
            for (int jj2 = 0; jj2 < 25; jj2++) {
                int jq = hhf * 25 + jj2;
                s = fmaf(hnf[(jq >> 1) * 32 + bfc * 2 + (jq & 1)], fcw[jq], s);
            }
            s += __shfl_xor_sync(0xffffffffu, s, 16);
            if (hhf == 0) {
                float y = s + fcb[0];
                hnf[25 * 32 + bfc * 2] = y;           // x slot k=50
                out[(size_t)(b0g + bfc) * T + t] = y;
            }
        }
        pb ^= 1;
        __syncthreads();
    }
}

extern "C" void kernel_launch(void* const* d_in, const int* in_sizes, int n_in,
                              void* d_out, int out_size)
{
    const float* source = (const float*)d_in[0];
    const float* eWih = (const float*)d_in[1];
    const float* eWhh = (const float*)d_in[2];
    const float* eBih = (const float*)d_in[3];
    const float* eBhh = (const float*)d_in[4];
    const float* dWih = (const float*)d_in[5];
    const float* dWhh = (const float*)d_in[6];
    const float* dBih = (const float*)d_in[7];
    const float* dBhh = (const float*)d_in[8];
    const float* fcW  = (const float*)d_in[9];
    const float* fcB  = (const float*)d_in[10];
    float* out = (float*)d_out;

    const int B = 2048;
    const int S = in_sizes[0] / B;   // 512
    const int T = out_size   / B;    // 256

    size_t sm = sizeof(float4) * (size_t)(K4N * 4 * JP * 2)
              + sizeof(u64)    * (size_t)(2 * HB)
              + sizeof(float)  * (size_t)(4 * JP * GSF + HID + 2)
              + sizeof(float)  * (size_t)BT * S;

    cudaFuncSetAttribute(seq2seq_kernel, cudaFuncAttributeMaxDynamicSharedMemorySize, (int)sm);
    seq2seq_kernel<<<B / BT, NTHREADS, sm>>>(source, eWih, eWhh, eBih, eBhh,
                                             dWih, dWhh, dBih, dBhh, fcW, fcB,
                                             out, S, T);
}

// round 15
// speedup vs baseline: 2.9363x; 2.0320x over previous
#include <cuda_runtime.h>
#include <cuda_bf16.h>
#include <cstdint>

#define HID 50
#define GP  224        // gates padded: g = ty*56 + j
#define GS  18         // gates u32 stride
#define BT  16
#define NKT 7          // k-tiles of 8: k in [0,56); k=50 is x slot
#define NTHREADS 512   // warps 0..13 GEMM (M-tile = wrp), 14 fc, update tid<400

// smem u32 offsets
#define OG   0                       // gates [224][18] f32
#define OBH  (GP * GS)               // B hi: [k2(28)][n(16)] u32(bf16x2)
#define OBL  (OBH + 28 * 16)
#define OHL  (OBL + 28 * 16)         // hlin [16][51] f32
#define OFC  (OHL + 16 * 51)         // fcw[50], fcb
#define OSRC (OFC + 52)              // srcsT [S][16] f32

__device__ __forceinline__ void mma_bf16(float* c, uint32_t a0, uint32_t a1, uint32_t b0) {
    asm volatile(
        "mma.sync.aligned.m16n8k8.row.col.f32.bf16.bf16.f32 "
        "{%0,%1,%2,%3}, {%4,%5}, {%6}, {%0,%1,%2,%3};"
        : "+f"(c[0]), "+f"(c[1]), "+f"(c[2]), "+f"(c[3])
        : "r"(a0), "r"(a1), "r"(b0));
}
__device__ __forceinline__ uint32_t pack2(float x, float y) {   // low=first
    return ((uint32_t)__bfloat16_as_ushort(__float2bfloat16(y)) << 16)
         | (uint32_t)__bfloat16_as_ushort(__float2bfloat16(x));
}
__device__ __forceinline__ float bhi(float x) {
    return __bfloat162float(__float2bfloat16(x));
}
__device__ __forceinline__ float tanh_a(float x) {
    float r; asm("tanh.approx.f32 %0, %1;" : "=f"(r) : "f"(x)); return r;
}
__device__ __forceinline__ float sigmoid_a(float x) {
    return fmaf(0.5f, tanh_a(0.5f * x), 0.5f);
}

__global__ void __launch_bounds__(NTHREADS, 1)
seq2seq_kernel(const float* __restrict__ source,
               const float* __restrict__ eWih, const float* __restrict__ eWhh,
               const float* __restrict__ eBih, const float* __restrict__ eBhh,
               const float* __restrict__ dWih, const float* __restrict__ dWhh,
               const float* __restrict__ dBih, const float* __restrict__ dBhh,
               const float* __restrict__ fcW,  const float* __restrict__ fcB,
               float* __restrict__ out, int S, int T)
{
    extern __shared__ uint32_t sm4[];
    float*    gatesf = (float*)(sm4 + OG);
    uint32_t* Bph    = sm4 + OBH;
    uint32_t* Bpl    = sm4 + OBL;
    float*    hlin   = (float*)(sm4 + OHL);
    float*    fcw    = (float*)(sm4 + OFC);
    float*    srcsT  = (float*)(sm4 + OSRC);

    const int tid  = threadIdx.x;
    const int lane = tid & 31;
    const int wrp  = tid >> 5;
    const int b0g  = blockIdx.x * BT;

    // GEMM roles (warps 0..13): M-tile = wrp, rows gA = wrp*16 + lane/4 (+8)
    const int gA = wrp * 16 + (lane >> 2);
    const int l4 = lane & 3;

    // ---- weight value for padded gate row g, k column
    auto wval = [&](const float* Whh, const float* Wih, int g, int k) -> float {
        int ty = g / 56, j = g % 56;
        if (j >= HID) return 0.f;
        int row = ty * HID + j;
        if (k < HID)  return Whh[row * HID + k];
        if (k == HID) return Wih[row];
        return 0.f;
    };

    // ---- A fragments (weights) live in registers for the whole phase
    uint32_t ah0[NKT], ah1[NKT], al0[NKT], al1[NKT];
    auto load_A = [&](const float* Whh, const float* Wih) {
        if (wrp < 14) {
            #pragma unroll
            for (int kt = 0; kt < NKT; kt++) {
                int k0 = kt * 8 + l4 * 2;
                float wA0 = wval(Whh, Wih, gA,     k0);
                float wA1 = wval(Whh, Wih, gA,     k0 + 1);
                float wB0 = wval(Whh, Wih, gA + 8, k0);
                float wB1 = wval(Whh, Wih, gA + 8, k0 + 1);
                ah0[kt] = pack2(wA0, wA1);
                ah1[kt] = pack2(wB0, wB1);
                al0[kt] = pack2(wA0 - bhi(wA0), wA1 - bhi(wA1));
                al1[kt] = pack2(wB0 - bhi(wB0), wB1 - bhi(wB1));
            }
        }
    };
    load_A(eWhh, eWih);

    // ---- init smem
    for (int i = tid; i < 2 * 28 * 16; i += NTHREADS) sm4[OBH + i] = 0u;  // B hi+lo
    if (tid < HID) fcw[tid] = fcW[tid];
    if (tid == 50) fcw[50] = fcB[0];
    for (int idx = tid; idx < BT * S; idx += NTHREADS) {
        int bl = idx / S, t = idx % S;
        srcsT[t * BT + bl] = source[(size_t)(b0g + bl) * S + t];
    }
    __syncthreads();
    if (tid < BT) {                         // x0 into k=50 slot (k2=25, low half)
        float x = srcsT[0 * BT + tid];
        Bph[25 * 16 + tid] = pack2(x, 0.f);
        Bpl[25 * 16 + tid] = pack2(x - bhi(x), 0.f);
    }

    // ---- update role: tid<400 -> (b = tid&15, j2 = tid>>4 in [0,25))
    const int bu = tid & 15, j2 = tid >> 4;
    const bool isupd = tid < 400;
    float ce = 0.f, co = 0.f;
    float be[4], bo[4];
    auto load_bias = [&](const float* Bih, const float* Bhh) {
        if (isupd) {
            #pragma unroll
            for (int ty = 0; ty < 4; ty++) {
                int r = ty * HID + 2 * j2;
                be[ty] = Bih[r] + Bhh[r];
                bo[ty] = Bih[r + 1] + Bhh[r + 1];
            }
        }
    };
    load_bias(eBih, eBhh);
    __syncthreads();

    // ---- GEMM: 14 warps, each 16 gate rows x 16 batch, K=56, 3-pass hi/lo
    auto gemm = [&]() {
        if (wrp < 14) {
            float c0[4] = {0.f, 0.f, 0.f, 0.f};
            float c1[4] = {0.f, 0.f, 0.f, 0.f};
            const int nb = lane >> 2;       // n within n-tile
            #pragma unroll
            for (int kt = 0; kt < NKT; kt++) {
                int k2 = kt * 4 + l4;
                uint32_t bh0 = Bph[k2 * 16 + nb];
                uint32_t bh1 = Bph[k2 * 16 + nb + 8];
                uint32_t bl0_ = Bpl[k2 * 16 + nb];
                uint32_t bl1_ = Bpl[k2 * 16 + nb + 8];
                mma_bf16(c0, ah0[kt], ah1[kt], bh0);
                mma_bf16(c1, ah0[kt], ah1[kt], bh1);
                mma_bf16(c0, ah0[kt], ah1[kt], bl0_);
                mma_bf16(c1, ah0[kt], ah1[kt], bl1_);
                mma_bf16(c0, al0[kt], al1[kt], bh0);
                mma_bf16(c1, al0[kt], al1[kt], bh1);
            }
            int n0 = l4 * 2;
            *(float2*)&gatesf[gA * GS + n0]           = make_float2(c0[0], c0[1]);
            *(float2*)&gatesf[(gA + 8) * GS + n0]     = make_float2(c0[2], c0[3]);
            *(float2*)&gatesf[gA * GS + 8 + n0]       = make_float2(c1[0], c1[1]);
            *(float2*)&gatesf[(gA + 8) * GS + 8 + n0] = make_float2(c1[2], c1[3]);
        }
    };

    // ---- update: thread handles cells (bu, 2*j2) and (bu, 2*j2+1)
    auto update = [&]() {
        if (isupd) {
            float ge[4], go[4];
            #pragma unroll
            for (int ty = 0; ty < 4; ty++) {
                int g = ty * 56 + 2 * j2;
                ge[ty] = gatesf[g * GS + bu] + be[ty];
                go[ty] = gatesf[(g + 1) * GS + bu] + bo[ty];
            }
            float ie = sigmoid_a(ge[0]), fe = sigmoid_a(ge[1]);
            float gve = tanh_a(ge[2]),   oe = sigmoid_a(ge[3]);
            ce = fmaf(fe, ce, ie * gve);
            float he = oe * tanh_a(ce);
            float io = sigmoid_a(go[0]), fo = sigmoid_a(go[1]);
            float gvo = tanh_a(go[2]),   oo = sigmoid_a(go[3]);
            co = fmaf(fo, co, io * gvo);
            float ho = oo * tanh_a(co);
            Bph[j2 * 16 + bu] = pack2(he, ho);
            Bpl[j2 * 16 + bu] = pack2(he - bhi(he), ho - bhi(ho));
            hlin[bu * 51 + 2 * j2]     = he;
            hlin[bu * 51 + 2 * j2 + 1] = ho;
        }
    };

    // ================= encoder =================
    for (int t = 0; t < S; t++) {
        gemm();
        __syncthreads();
        update();
        if (tid < BT) {                     // x_{t+1}; t=S-1 writes 0 = decoder x0
            float x = (t + 1 < S) ? srcsT[(t + 1) * BT + tid] : 0.f;
            Bph[25 * 16 + tid] = pack2(x, 0.f);
            Bpl[25 * 16 + tid] = pack2(x - bhi(x), 0.f);
        }
        __syncthreads();
    }

    // ================= switch to decoder =================
    load_A(dWhh, dWih);
    load_bias(dBih, dBhh);
    __syncthreads();

    // ================= decoder =================
    for (int t = 0; t < T; t++) {
        gemm();
        __syncthreads();
        update();
        __syncthreads();                    // hlin visible
        if (wrp == 14) {                    // fc + feedback (warp idle in GEMM)
            const int bfc = lane & 15;
            const int hhf = lane >> 4;
            float s = 0.f;
            #pragma unroll
            for (int jj = 0; jj < 25; jj++) {
                int jq = hhf * 25 + jj;
                s = fmaf(hlin[bfc * 51 + jq], fcw[jq], s);
            }
            s += __shfl_xor_sync(0xffffffffu, s, 16);
            if (hhf == 0) {
                float y = s + fcw[50];
                out[(size_t)(b0g + bfc) * T + t] = y;
                Bph[25 * 16 + bfc] = pack2(y, 0.f);
                Bpl[25 * 16 + bfc] = pack2(y - bhi(y), 0.f);
            }
        }
        __syncthreads();
    }
}

extern "C" void kernel_launch(void* const* d_in, const int* in_sizes, int n_in,
                              void* d_out, int out_size)
{
    const float* source = (const float*)d_in[0];
    const float* eWih = (const float*)d_in[1];
    const float* eWhh = (const float*)d_in[2];
    const float* eBih = (const float*)d_in[3];
    const float* eBhh = (const float*)d_in[4];
    const float* dWih = (const float*)d_in[5];
    const float* dWhh = (const float*)d_in[6];
    const float* dBih = (const float*)d_in[7];
    const float* dBhh = (const float*)d_in[8];
    const float* fcW  = (const float*)d_in[9];
    const float* fcB  = (const float*)d_in[10];
    float* out = (float*)d_out;

    const int B = 2048;
    const int S = in_sizes[0] / B;   // 512
    const int T = out_size   / B;    // 256

    size_t smem = sizeof(uint32_t) * ((size_t)OSRC + (size_t)S * BT);
    cudaFuncSetAttribute(seq2seq_kernel, cudaFuncAttributeMaxDynamicSharedMemorySize, (int)smem);
    seq2seq_kernel<<<B / BT, NTHREADS, smem>>>(source, eWih, eWhh, eBih, eBhh,
                                               dWih, dWhh, dBih, dBhh, fcW, fcB,
                                               out, S, T);
}

// round 16
// speedup vs baseline: 3.2212x; 1.0971x over previous
#include <cuda_runtime.h>
#include <cuda_bf16.h>
#include <cstdint>

#define HID 50
#define GP  240        // gates padded: g = ty*60 + j, 15 M-tiles of 16
#define GS  18         // gates f32 stride
#define BT  16
#define NKT 4          // k-tiles of 16: K=64; k=50 is x slot, 51..63 zero
#define NTHREADS 512   // warps 0..14 GEMM, warp 15 fc; update tid<400

// smem u32 offsets
#define OG   0                       // gates [240][18] f32
#define OBH  (GP * GS)               // B hi: [k2(32)][n(16)] u32(bf16x2)
#define OBL  (OBH + 32 * 16)
#define OHL  (OBL + 32 * 16)         // hlin [16][51] f32
#define OFC  (OHL + 16 * 51)         // fcw[50], fcb
#define OSRC (OFC + 52)              // srcsT [S][16] f32

__device__ __forceinline__ void mma16(float* c, const uint32_t* a, uint32_t b0, uint32_t b1) {
    asm volatile(
        "mma.sync.aligned.m16n8k16.row.col.f32.bf16.bf16.f32 "
        "{%0,%1,%2,%3}, {%4,%5,%6,%7}, {%8,%9}, {%0,%1,%2,%3};"
        : "+f"(c[0]), "+f"(c[1]), "+f"(c[2]), "+f"(c[3])
        : "r"(a[0]), "r"(a[1]), "r"(a[2]), "r"(a[3]), "r"(b0), "r"(b1));
}
__device__ __forceinline__ uint32_t pack2(float x, float y) {
    return ((uint32_t)__bfloat16_as_ushort(__float2bfloat16(y)) << 16)
         | (uint32_t)__bfloat16_as_ushort(__float2bfloat16(x));
}
__device__ __forceinline__ float bhi(float x) {
    return __bfloat162float(__float2bfloat16(x));
}
__device__ __forceinline__ float tanh_a(float x) {
    float r; asm("tanh.approx.f32 %0, %1;" : "=f"(r) : "f"(x)); return r;
}
__device__ __forceinline__ float sigmoid_a(float x) {
    return fmaf(0.5f, tanh_a(0.5f * x), 0.5f);
}

__global__ void __launch_bounds__(NTHREADS, 1)
seq2seq_kernel(const float* __restrict__ source,
               const float* __restrict__ eWih, const float* __restrict__ eWhh,
               const float* __restrict__ eBih, const float* __restrict__ eBhh,
               const float* __restrict__ dWih, const float* __restrict__ dWhh,
               const float* __restrict__ dBih, const float* __restrict__ dBhh,
               const float* __restrict__ fcW,  const float* __restrict__ fcB,
               float* __restrict__ out, int S, int T)
{
    extern __shared__ uint32_t sm4[];
    float*    gatesf = (float*)(sm4 + OG);
    uint32_t* Bph    = sm4 + OBH;
    uint32_t* Bpl    = sm4 + OBL;
    float*    hlin   = (float*)(sm4 + OHL);
    float*    fcw    = (float*)(sm4 + OFC);
    float*    srcsT  = (float*)(sm4 + OSRC);

    const int tid  = threadIdx.x;
    const int lane = tid & 31;
    const int wrp  = tid >> 5;
    const int b0g  = blockIdx.x * BT;

    // GEMM roles (warps 0..14): M-tile = wrp, A rows gA, gA+8
    const int gA = wrp * 16 + (lane >> 2);
    const int l4 = lane & 3;
    const int nb = lane >> 2;               // B col within n-half

    auto wval = [&](const float* Whh, const float* Wih, int g, int k) -> float {
        int ty = g / 60, j = g % 60;
        if (j >= HID) return 0.f;
        int row = ty * HID + j;
        if (k < HID)  return Whh[row * HID + k];
        if (k == HID) return Wih[row];
        return 0.f;
    };

    // ---- A fragments in registers for the whole phase (m16n8k16: 4 regs)
    uint32_t ah[NKT][4], al[NKT][4];
    auto load_A = [&](const float* Whh, const float* Wih) {
        if (wrp < 15) {
            #pragma unroll
            for (int kt = 0; kt < NKT; kt++) {
                int k0 = kt * 16 + l4 * 2;
                #pragma unroll
                for (int q = 0; q < 4; q++) {
                    int row = gA + ((q & 1) ? 8 : 0);
                    int kk  = k0 + ((q & 2) ? 8 : 0);
                    float w0 = wval(Whh, Wih, row, kk);
                    float w1 = wval(Whh, Wih, row, kk + 1);
                    ah[kt][q] = pack2(w0, w1);
                    al[kt][q] = pack2(w0 - bhi(w0), w1 - bhi(w1));
                }
            }
        }
    };
    load_A(eWhh, eWih);

    // ---- init smem
    for (int i = tid; i < 2 * 32 * 16; i += NTHREADS) sm4[OBH + i] = 0u;
    if (tid < HID) fcw[tid] = fcW[tid];
    if (tid == 50) fcw[50] = fcB[0];
    for (int idx = tid; idx < BT * S; idx += NTHREADS) {
        int bl = idx / S, t = idx % S;
        srcsT[t * BT + bl] = source[(size_t)(b0g + bl) * S + t];
    }
    __syncthreads();
    if (tid < BT) {                          // x0 into k=50 (k2=25, low half)
        float x = srcsT[0 * BT + tid];
        Bph[25 * 16 + tid] = pack2(x, 0.f);
        Bpl[25 * 16 + tid] = pack2(x - bhi(x), 0.f);
    }

    // ---- update role: tid<400 -> (b = tid&15, j2 = tid>>4 in [0,25))
    const int bu = tid & 15, j2 = tid >> 4;
    const bool isupd = tid < 400;
    float ce = 0.f, co = 0.f;
    float be[4], bo[4];
    auto load_bias = [&](const float* Bih, const float* Bhh) {
        if (isupd) {
            #pragma unroll
            for (int ty = 0; ty < 4; ty++) {
                int r = ty * HID + 2 * j2;
                be[ty] = Bih[r] + Bhh[r];
                bo[ty] = Bih[r + 1] + Bhh[r + 1];
            }
        }
    };
    load_bias(eBih, eBhh);
    __syncthreads();

    // ---- GEMM: split accumulators (main = hi*hi, corr = hi*lo + lo*hi)
    auto gemm = [&]() {
        if (wrp < 15) {
            float cm0[4] = {0,0,0,0}, cc0[4] = {0,0,0,0};
            float cm1[4] = {0,0,0,0}, cc1[4] = {0,0,0,0};
            #pragma unroll
            for (int kt = 0; kt < NKT; kt++) {
                int k2a = kt * 8 + l4;       // b0 k-pair
                int k2b = k2a + 4;           // b1 k-pair
                uint32_t bh0a = Bph[k2a * 16 + nb],     bh1a = Bph[k2b * 16 + nb];
                uint32_t bh0b = Bph[k2a * 16 + nb + 8], bh1b = Bph[k2b * 16 + nb + 8];
                uint32_t bl0a = Bpl[k2a * 16 + nb],     bl1a = Bpl[k2b * 16 + nb];
                uint32_t bl0b = Bpl[k2a * 16 + nb + 8], bl1b = Bpl[k2b * 16 + nb + 8];
                mma16(cm0, ah[kt], bh0a, bh1a);
                mma16(cm1, ah[kt], bh0b, bh1b);
                mma16(cc0, ah[kt], bl0a, bl1a);
                mma16(cc1, ah[kt], bl0b, bl1b);
                mma16(cc0, al[kt], bh0a, bh1a);
                mma16(cc1, al[kt], bh0b, bh1b);
            }
            int n0 = l4 * 2;
            *(float2*)&gatesf[gA * GS + n0] =
                make_float2(cm0[0] + cc0[0], cm0[1] + cc0[1]);
            *(float2*)&gatesf[(gA + 8) * GS + n0] =
                make_float2(cm0[2] + cc0[2], cm0[3] + cc0[3]);
            *(float2*)&gatesf[gA * GS + 8 + n0] =
                make_float2(cm1[0] + cc1[0], cm1[1] + cc1[1]);
            *(float2*)&gatesf[(gA + 8) * GS + 8 + n0] =
                make_float2(cm1[2] + cc1[2], cm1[3] + cc1[3]);
        }
    };

    // ---- update: thread handles cells (bu, 2*j2) and (bu, 2*j2+1)
    auto update = [&]() {
        if (isupd) {
            float ge[4], go[4];
            #pragma unroll
            for (int ty = 0; ty < 4; ty++) {
                int g = ty * 60 + 2 * j2;
                ge[ty] = gatesf[g * GS + bu] + be[ty];
                go[ty] = gatesf[(g + 1) * GS + bu] + bo[ty];
            }
            float ie = sigmoid_a(ge[0]), fe = sigmoid_a(ge[1]);
            float gve = tanh_a(ge[2]),   oe = sigmoid_a(ge[3]);
            ce = fmaf(fe, ce, ie * gve);
            float he = oe * tanh_a(ce);
            float io = sigmoid_a(go[0]), fo = sigmoid_a(go[1]);
            float gvo = tanh_a(go[2]),   oo = sigmoid_a(go[3]);
            co = fmaf(fo, co, io * gvo);
            float ho = oo * tanh_a(co);
            Bph[j2 * 16 + bu] = pack2(he, ho);
            Bpl[j2 * 16 + bu] = pack2(he - bhi(he), ho - bhi(ho));
            hlin[bu * 51 + 2 * j2]     = he;
            hlin[bu * 51 + 2 * j2 + 1] = ho;
        }
    };

    // ================= encoder =================
    for (int t = 0; t < S; t++) {
        gemm();
        __syncthreads();
        update();
        if (tid < BT) {                      // x_{t+1}; t=S-1 writes 0 = decoder x0
            float x = (t + 1 < S) ? srcsT[(t + 1) * BT + tid] : 0.f;
            Bph[25 * 16 + tid] = pack2(x, 0.f);
            Bpl[25 * 16 + tid] = pack2(x - bhi(x), 0.f);
        }
        __syncthreads();
    }

    // ================= switch to decoder =================
    load_A(dWhh, dWih);
    load_bias(dBih, dBhh);
    __syncthreads();

    // ================= decoder =================
    for (int t = 0; t < T; t++) {
        gemm();
        __syncthreads();
        update();
        __syncthreads();                     // hlin visible
        if (wrp == 15) {                     // fc + feedback (GEMM-idle warp)
            const int bfc = lane & 15;
            const int hhf = lane >> 4;
            float s = 0.f;
            #pragma unroll
            for (int jj = 0; jj < 25; jj++) {
                int jq = hhf * 25 + jj;
                s = fmaf(hlin[bfc * 51 + jq], fcw[jq], s);
            }
            s += __shfl_xor_sync(0xffffffffu, s, 16);
            if (hhf == 0) {
                float y = s + fcw[50];
                out[(size_t)(b0g + bfc) * T + t] = y;
                Bph[25 * 16 + bfc] = pack2(y, 0.f);
                Bpl[25 * 16 + bfc] = pack2(y - bhi(y), 0.f);
            }
        }
        __syncthreads();
    }
}

extern "C" void kernel_launch(void* const* d_in, const int* in_sizes, int n_in,
                              void* d_out, int out_size)
{
    const float* source = (const float*)d_in[0];
    const float* eWih = (const float*)d_in[1];
    const float* eWhh = (const float*)d_in[2];
    const float* eBih = (const float*)d_in[3];
    const float* eBhh = (const float*)d_in[4];
    const float* dWih = (const float*)d_in[5];
    const float* dWhh = (const float*)d_in[6];
    const float* dBih = (const float*)d_in[7];
    const float* dBhh = (const float*)d_in[8];
    const float* fcW  = (const float*)d_in[9];
    const float* fcB  = (const float*)d_in[10];
    float* out = (float*)d_out;

    const int B = 2048;
    const int S = in_sizes[0] / B;   // 512
    const int T = out_size   / B;    // 256

    size_t smem = sizeof(uint32_t) * ((size_t)OSRC + (size_t)S * BT);
    cudaFuncSetAttribute(seq2seq_kernel, cudaFuncAttributeMaxDynamicSharedMemorySize, (int)smem);
    seq2seq_kernel<<<B / BT, NTHREADS, smem>>>(source, eWih, eWhh, eBih, eBhh,
                                               dWih, dWhh, dBih, dBhh, fcW, fcB,
                                               out, S, T);
}

// round 17
// speedup vs baseline: 4.0479x; 1.2566x over previous
#include <cuda_runtime.h>
#include <cuda_bf16.h>
#include <cstdint>

#define HID 50
#define BT  16
#define HS  36              // u32 stride per batch row in h buffers (conflict-free)
#define HBUF (BT * HS)      // 576 u32 per buffer
#define NTHREADS 512        // warps 0..14 GEMM+update, warp 15 x-feed / fc

// smem u32 offsets
#define OHH  0                       // Hhi [2][HBUF]
#define OHL  (2 * HBUF)              // Hlo [2][HBUF]
#define OFC  (4 * HBUF)              // fcw[50], fcb @50
#define OSRC (OFC + 52)              // srcsT [S][16] f32

__device__ __forceinline__ void mma16(float* c, const uint32_t* a, uint32_t b0, uint32_t b1) {
    asm volatile(
        "mma.sync.aligned.m16n8k16.row.col.f32.bf16.bf16.f32 "
        "{%0,%1,%2,%3}, {%4,%5,%6,%7}, {%8,%9}, {%0,%1,%2,%3};"
        : "+f"(c[0]), "+f"(c[1]), "+f"(c[2]), "+f"(c[3])
        : "r"(a[0]), "r"(a[1]), "r"(a[2]), "r"(a[3]), "r"(b0), "r"(b1));
}
__device__ __forceinline__ uint32_t pack2(float x, float y) {
    return ((uint32_t)__bfloat16_as_ushort(__float2bfloat16(y)) << 16)
         | (uint32_t)__bfloat16_as_ushort(__float2bfloat16(x));
}
__device__ __forceinline__ float bhi(float x) {
    return __bfloat162float(__float2bfloat16(x));
}
__device__ __forceinline__ float tanh_a(float x) {
    float r; asm("tanh.approx.f32 %0, %1;" : "=f"(r) : "f"(x)); return r;
}
__device__ __forceinline__ float sigmoid_a(float x) {
    return fmaf(0.5f, tanh_a(0.5f * x), 0.5f);
}

__global__ void __launch_bounds__(NTHREADS, 1)
seq2seq_kernel(const float* __restrict__ source,
               const float* __restrict__ eWih, const float* __restrict__ eWhh,
               const float* __restrict__ eBih, const float* __restrict__ eBhh,
               const float* __restrict__ dWih, const float* __restrict__ dWhh,
               const float* __restrict__ dBih, const float* __restrict__ dBhh,
               const float* __restrict__ fcW,  const float* __restrict__ fcB,
               float* __restrict__ out, int S, int T)
{
    extern __shared__ uint32_t sm4[];
    uint32_t* HH   = sm4 + OHH;          // hi h buffers [2][HBUF]
    uint32_t* HL   = sm4 + OHL;          // lo h buffers
    float*    fcw  = (float*)(sm4 + OFC);
    float*    srcsT= (float*)(sm4 + OSRC);

    const int tid  = threadIdx.x;
    const int lane = tid & 31;
    const int wrp  = tid >> 5;
    const int b0g  = blockIdx.x * BT;

    const int t4 = lane & 3;             // MMA quad col / cell j offset
    const int r0 = lane >> 2;            // MMA row group (= batch row / B col n)
    const int jme = wrp * 4 + t4;        // this thread's cell j
    const bool gw  = wrp < 15;
    const bool upd = gw && (jme < HID);

    // ---- W fragments in registers: B operand, col n = r0 within each 8-tile
    // tile tt: col n -> gate (j = wrp*4 + (n>>1), ty = tt*2 + (n&1))
    uint32_t wfh[2][4][2], wfl[2][4][2];
    auto wval = [&](const float* Whh, const float* Wih, int ty, int j, int k) -> float {
        if (j >= HID) return 0.f;
        int row = ty * HID + j;
        if (k < HID)  return Whh[row * HID + k];
        if (k == HID) return Wih[row];
        return 0.f;
    };
    auto load_W = [&](const float* Whh, const float* Wih) {
        if (gw) {
            int j  = wrp * 4 + (r0 >> 1);
            #pragma unroll
            for (int tt = 0; tt < 2; tt++) {
                int ty = tt * 2 + (r0 & 1);
                #pragma unroll
                for (int kt = 0; kt < 4; kt++) {
                    int k0 = kt * 16 + 2 * t4;
                    float w0 = wval(Whh, Wih, ty, j, k0);
                    float w1 = wval(Whh, Wih, ty, j, k0 + 1);
                    float w2 = wval(Whh, Wih, ty, j, k0 + 8);
                    float w3 = wval(Whh, Wih, ty, j, k0 + 9);
                    wfh[tt][kt][0] = pack2(w0, w1);
                    wfh[tt][kt][1] = pack2(w2, w3);
                    wfl[tt][kt][0] = pack2(w0 - bhi(w0), w1 - bhi(w1));
                    wfl[tt][kt][1] = pack2(w2 - bhi(w2), w3 - bhi(w3));
                }
            }
        }
    };
    load_W(eWhh, eWih);

    float bias[4];
    auto load_bias = [&](const float* Bih, const float* Bhh) {
        if (upd) {
            #pragma unroll
            for (int ty = 0; ty < 4; ty++) {
                int r = ty * HID + jme;
                bias[ty] = Bih[r] + Bhh[r];
            }
        }
    };
    load_bias(eBih, eBhh);

    // ---- init smem
    for (int i = tid; i < 4 * HBUF; i += NTHREADS) sm4[i] = 0u;
    if (tid < HID) fcw[tid] = fcW[tid];
    if (tid == 50) fcw[50] = fcB[0];
    for (int idx = tid; idx < BT * S; idx += NTHREADS) {
        int bl = idx / S, t = idx % S;
        srcsT[t * BT + bl] = source[(size_t)(b0g + bl) * S + t];
    }
    __syncthreads();
    if (tid < BT) {                      // x0 into buf0 slot k2=25
        float x = srcsT[0 * BT + tid];
        HH[tid * HS + 25] = pack2(x, 0.f);
        HL[tid * HS + 25] = pack2(x - bhi(x), 0.f);
    }
    float ce = 0.f, co = 0.f;            // cell states for (r0, jme), (r0+8, jme)
    __syncthreads();

    // ---- GEMM: A = h (hi/lo from smem), B = W frags; outputs cell gates in regs
    float g0[4], g1[4];
    auto gemm = [&](const uint32_t* Hh, const uint32_t* Hl) {
        if (!gw) return;
        float cm0[4] = {0,0,0,0}, cm1[4] = {0,0,0,0};
        float cc0[4] = {0,0,0,0}, cc1[4] = {0,0,0,0};
        #pragma unroll
        for (int kt = 0; kt < 4; kt++) {
            int base = r0 * HS + kt * 8 + t4;
            uint32_t ahi[4], alo[4];
            ahi[0] = Hh[base];            ahi[1] = Hh[base + 8 * HS];
            ahi[2] = Hh[base + 4];        ahi[3] = Hh[base + 8 * HS + 4];
            alo[0] = Hl[base];            alo[1] = Hl[base + 8 * HS];
            alo[2] = Hl[base + 4];        alo[3] = Hl[base + 8 * HS + 4];
            mma16(cm0, ahi, wfh[0][kt][0], wfh[0][kt][1]);
            mma16(cm1, ahi, wfh[1][kt][0], wfh[1][kt][1]);
            mma16(cc0, ahi, wfl[0][kt][0], wfl[0][kt][1]);
            mma16(cc1, ahi, wfl[1][kt][0], wfl[1][kt][1]);
            mma16(cc0, alo, wfh[0][kt][0], wfh[0][kt][1]);
            mma16(cc1, alo, wfh[1][kt][0], wfh[1][kt][1]);
        }
        // cell0 = (batch r0, jme): C row r0, cols 2t4/2t4+1 of tiles A,B
        g0[0] = cm0[0] + cc0[0];  g0[1] = cm0[1] + cc0[1];
        g0[2] = cm1[0] + cc1[0];  g0[3] = cm1[1] + cc1[1];
        // cell1 = (batch r0+8, jme)
        g1[0] = cm0[2] + cc0[2];  g1[1] = cm0[3] + cc0[3];
        g1[2] = cm1[2] + cc1[2];  g1[3] = cm1[3] + cc1[3];
    };

    auto update = [&](const float* g, float& c, int b,
                      __nv_bfloat16* Hhn, __nv_bfloat16* Hln) {
        float iv = sigmoid_a(g[0] + bias[0]);
        float fv = sigmoid_a(g[1] + bias[1]);
        float gv = tanh_a(g[2] + bias[2]);
        float ov = sigmoid_a(g[3] + bias[3]);
        c = fmaf(fv, c, iv * gv);
        float h = ov * tanh_a(c);
        int idx = (b * HS + (jme >> 1)) * 2 + (jme & 1);
        __nv_bfloat16 hi = __float2bfloat16(h);
        Hhn[idx] = hi;
        Hln[idx] = __float2bfloat16(h - __bfloat162float(hi));
    };

    int pb = 0;

    // ================= encoder: ONE barrier per step =================
    for (int t = 0; t < S; t++) {
        gemm(HH + pb * HBUF, HL + pb * HBUF);
        __nv_bfloat16* Hhn = (__nv_bfloat16*)(HH + (pb ^ 1) * HBUF);
        __nv_bfloat16* Hln = (__nv_bfloat16*)(HL + (pb ^ 1) * HBUF);
        if (upd) {
            update(g0, ce, r0, Hhn, Hln);
            update(g1, co, r0 + 8, Hhn, Hln);
        }
        if (wrp == 15 && lane < 16) {    // x_{t+1}; t=S-1 writes 0 = decoder x0
            float x = (t + 1 < S) ? srcsT[(t + 1) * BT + lane] : 0.f;
            ((uint32_t*)Hhn)[lane * HS + 25] = pack2(x, 0.f);
            ((uint32_t*)Hln)[lane * HS + 25] = pack2(x - bhi(x), 0.f);
        }
        pb ^= 1;
        __syncthreads();
    }

    // ================= switch to decoder =================
    load_W(dWhh, dWih);
    load_bias(dBih, dBhh);
    __syncthreads();

    // ================= decoder: two barriers per step =================
    for (int t = 0; t < T; t++) {
        gemm(HH + pb * HBUF, HL + pb * HBUF);
        __nv_bfloat16* Hhn = (__nv_bfloat16*)(HH + (pb ^ 1) * HBUF);
        __nv_bfloat16* Hln = (__nv_bfloat16*)(HL + (pb ^ 1) * HBUF);
        if (upd) {
            update(g0, ce, r0, Hhn, Hln);
            update(g1, co, r0 + 8, Hhn, Hln);
        }
        __syncthreads();                 // h_t visible in buf pb^1
        if (wrp == 15) {                 // fc on h_t + feedback
            const int bfc = lane & 15;
            const int hhf = lane >> 4;
            const uint32_t* Hh2 = HH + (pb ^ 1) * HBUF;
            const uint32_t* Hl2 = HL + (pb ^ 1) * HBUF;
            float s = 0.f;
            #pragma unroll
            for (int jj = 0; jj < 25; jj++) {
                int jq = hhf * 25 + jj;
                uint32_t uh = Hh2[bfc * HS + (jq >> 1)];
                uint32_t ul = Hl2[bfc * HS + (jq >> 1)];
                uint16_t h16 = (jq & 1) ? (uint16_t)(uh >> 16) : (uint16_t)(uh & 0xffff);
                uint16_t l16 = (jq & 1) ? (uint16_t)(ul >> 16) : (uint16_t)(ul & 0xffff);
                float hv = __bfloat162float(__ushort_as_bfloat16(h16))
                         + __bfloat162float(__ushort_as_bfloat16(l16));
                s = fmaf(hv, fcw[jq], s);
            }
            s += __shfl_xor_sync(0xffffffffu, s, 16);
            if (hhf == 0) {
                float y = s + fcw[50];
                out[(size_t)(b0g + bfc) * T + t] = y;
                ((uint32_t*)Hh2)[bfc * HS + 25] = pack2(y, 0.f);
                ((uint32_t*)Hl2)[bfc * HS + 25] = pack2(y - bhi(y), 0.f);
            }
        }
        pb ^= 1;
        __syncthreads();
    }
}

extern "C" void kernel_launch(void* const* d_in, const int* in_sizes, int n_in,
                              void* d_out, int out_size)
{
    const float* source = (const float*)d_in[0];
    const float* eWih = (const float*)d_in[1];
    const float* eWhh = (const float*)d_in[2];
    const float* eBih = (const float*)d_in[3];
    const float* eBhh = (const float*)d_in[4];
    const float* dWih = (const float*)d_in[5];
    const float* dWhh = (const float*)d_in[6];
    const float* dBih = (const float*)d_in[7];
    const float* dBhh = (const float*)d_in[8];
    const float* fcW  = (const float*)d_in[9];
    const float* fcB  = (const float*)d_in[10];
    float* out = (float*)d_out;

    const int B = 2048;
    const int S = in_sizes[0] / B;   // 512
    const int T = out_size   / B;    // 256

    size_t smem = sizeof(uint32_t) * ((size_t)OSRC + (size_t)S * BT);
    cudaFuncSetAttribute(seq2seq_kernel, cudaFuncAttributeMaxDynamicSharedMemorySize, (int)smem);
    seq2seq_kernel<<<B / BT, NTHREADS, smem>>>(source, eWih, eWhh, eBih, eBhh,
                                               dWih, dWhh, dBih, dBhh, fcW, fcB,
                                               out, S, T);
}